// round 11
// baseline (speedup 1.0000x reference)
#include <cuda_runtime.h>

// PerturbedTopK: x (64,196) f32, noise (64,500,196) f32.
// out[b,k,d] = mean_n [ sorted(top49_idx(x_b + 0.05*noise_bn))[k] == d ].
//
// R11: grid (10,64) x 256; each block: 50 rows of one batch -> u16-packed
// shared histogram (halves <= 50, no carry), flushed with packed-u32 REDG
// into a static global accumulator (totals <= 500/half, no carry).
// Finalize kernel writes out = acc/500 and zeroes acc (graph-replay safe).
// Per-row: integer-key boundary-jump select seeded from the batch threshold
// of x; jumps use +-1 bookkeeping (exact for distinct keys) and a single
// final verification count; verification failure (ties) or cap -> exact MSB
// radix fallback with index-order tie-break. rel_err = 0 (integer counts).

#define BATCH 64
#define NSAMP 500
#define DIM   196
#define TOPK  49
#define SIGMA 0.05f

#define COPIES 10
#define ROWS_PB (NSAMP / COPIES)   // 50
#define HISTN (TOPK * DIM)         // 9604 cells
#define HISTW (HISTN / 2)          // 4802 packed words
#define FULLM 0xffffffffu
#define NEGBIG (-3.402823466e38f)

__device__ unsigned g_acc[BATCH][HISTW];   // static accumulator (zero-init)

__device__ __forceinline__ unsigned f2key(float v) {
    unsigned u = __float_as_uint(v);
    return u ^ ((unsigned)((int)u >> 31) | 0x80000000u);
}
__device__ __forceinline__ float key2f(unsigned k) {
    unsigned u = (k & 0x80000000u) ? (k ^ 0x80000000u) : ~k;
    return __uint_as_float(u);
}
__device__ __forceinline__ unsigned fgt(float a, float b) {
    unsigned r;
    asm("set.gt.u32.f32 %0, %1, %2;" : "=r"(r) : "f"(a), "f"(b));
    return r;
}
__device__ __forceinline__ unsigned ugt(unsigned a, unsigned b) {
    unsigned r;
    asm("set.gt.u32.u32 %0, %1, %2;" : "=r"(r) : "r"(a), "r"(b));
    return r;
}

__global__ __launch_bounds__(256)
void ptopk_main(const float* __restrict__ x,
                const float* __restrict__ noise) {
    __shared__ __align__(16) unsigned hist[HISTW];
    __shared__ unsigned sKseed;

    const int tid  = threadIdx.x;
    const int wid  = tid >> 5;
    const int lane = tid & 31;
    const int copy = blockIdx.x;
    const int b    = blockIdx.y;
    const unsigned lt  = (1u << lane) - 1u;
    const unsigned inc = 1u << ((lane & 1) << 4);   // u16 half by d parity

    for (int i = tid; i < HISTW; i += 256) hist[i] = 0;

    // x row resident in registers.
    float xv[7];
    #pragma unroll
    for (int j = 0; j < 7; j++) {
        const int d = j * 32 + lane;
        xv[j] = (d < DIM) ? x[b * DIM + d] : NEGBIG;
    }

    // Warp 0: batch seed threshold from x (hint only — any value is safe).
    if (wid == 0) {
        float piv = 0.674f;
        #pragma unroll 1
        for (int it = 0; it < 16; ++it) {
            unsigned a = 0;
            #pragma unroll
            for (int j = 0; j < 7; j++) a += fgt(xv[j], piv);
            const int c = -(int)__reduce_add_sync(FULLM, (int)a);
            if (c == TOPK) break;
            const int dd = c - TOPK;
            if (dd > 3 || dd < -3) {
                piv = fmaf((float)dd, 0.0161f, piv);       // Newton step
            } else if (dd > 0) {
                unsigned mk = 0xFFFFFFFFu;
                #pragma unroll
                for (int j = 0; j < 7; j++)
                    mk = min(mk, (xv[j] > piv) ? f2key(xv[j]) : 0xFFFFFFFFu);
                piv = key2f(__reduce_min_sync(FULLM, mk));
            } else {
                unsigned Mk = 0u;
                #pragma unroll
                for (int j = 0; j < 7; j++)
                    Mk = max(Mk, (xv[j] > piv) ? 0u : f2key(xv[j]));
                piv = key2f(__reduce_max_sync(FULLM, Mk) - 1u);
            }
        }
        if (lane == 0) sKseed = f2key(piv);
    }
    __syncthreads();
    const unsigned Kseed = sKseed;

    const size_t rowbase = (size_t)b * NSAMP + (size_t)copy * ROWS_PB;

    int r = wid;
    float nv[7];
    {
        const float* nr = noise + (rowbase + r) * DIM;
        #pragma unroll
        for (int j = 0; j < 7; j++) {
            const int d = j * 32 + lane;
            nv[j] = (d < DIM) ? nr[d] : 0.0f;
        }
    }

    #pragma unroll 1
    while (r < ROWS_PB) {
        const int rn = r + 8;
        float pv[7];
        if (rn < ROWS_PB) {                        // prefetch next row
            const float* nr2 = noise + (rowbase + rn) * DIM;
            #pragma unroll
            for (int j = 0; j < 7; j++) {
                const int d = j * 32 + lane;
                pv[j] = (d < DIM) ? nr2[d] : 0.0f;
            }
        }

        // Monotonic integer keys; padding -> 0 (below any real key).
        unsigned key[7];
        #pragma unroll
        for (int j = 0; j < 7; j++) {
            const int d = j * 32 + lane;
            key[j] = (d < DIM) ? f2key(fmaf(nv[j], SIGMA, xv[j])) : 0u;
        }

        // ---- boundary-jump select: +-1 bookkeeping, verify at end ----
        unsigned Kthr = Kseed;
        unsigned a = 0;
        #pragma unroll
        for (int j = 0; j < 7; j++) a += ugt(key[j], Kthr);
        int c = -(int)__reduce_add_sync(FULLM, (int)a);

        #pragma unroll 1
        for (int it = 0; it < 12 && c != TOPK; ++it) {
            if (c > TOPK) {
                unsigned mk = 0xFFFFFFFFu;         // min selected key
                #pragma unroll
                for (int j = 0; j < 7; j++)
                    mk = min(mk, (key[j] > Kthr) ? key[j] : 0xFFFFFFFFu);
                Kthr = __reduce_min_sync(FULLM, mk);
                c -= 1;                            // exact if keys distinct
            } else {
                unsigned Mk = 0u;                  // max unselected key
                #pragma unroll
                for (int j = 0; j < 7; j++)
                    Mk = max(Mk, (key[j] > Kthr) ? 0u : key[j]);
                Kthr = __reduce_max_sync(FULLM, Mk) - 1u;
                c += 1;                            // exact if keys distinct
            }
        }

        // Single verification count (catches any tie-induced drift).
        unsigned a2 = 0;
        #pragma unroll
        for (int j = 0; j < 7; j++) a2 += ugt(key[j], Kthr);
        const int cv = -(int)__reduce_add_sync(FULLM, (int)a2);

        if (cv == TOPK) {
            // Exactly TOPK strictly above: rank by ascending index.
            int base = 0;
            #pragma unroll
            for (int j = 0; j < 7; j++) {
                const int d = j * 32 + lane;
                const bool s = key[j] > Kthr;
                const unsigned mb = __ballot_sync(FULLM, s);
                if (s) {
                    const int rank = base + __popc(mb & lt);
                    atomicAdd(&hist[(rank * DIM + d) >> 1], inc);
                }
                base += __popc(mb);
            }
        } else {
            // ---- exact MSB radix fallback with index-order tie-break ----
            unsigned actm = (6 * 32 + lane < DIM) ? 0x7Fu : 0x3Fu;
            int k = TOPK, matching = DIM, s = 0;
            unsigned P = 0u;
            #pragma unroll 1
            for (int bit = 31; bit >= 0; --bit) {
                const unsigned m = 1u << bit;
                int cc = 0;
                #pragma unroll
                for (int j = 0; j < 7; j++)
                    cc += (((actm >> j) & 1u) && (key[j] & m)) ? 1 : 0;
                cc = __reduce_add_sync(FULLM, cc);
                if (cc >= k) {
                    P |= m; matching = cc;
                    #pragma unroll
                    for (int j = 0; j < 7; j++)
                        if (!(key[j] & m)) actm &= ~(1u << j);
                } else {
                    k -= cc; matching -= cc;
                    #pragma unroll
                    for (int j = 0; j < 7; j++)
                        if (key[j] & m) actm &= ~(1u << j);
                }
                s = bit;
                if (matching == k) break;
            }
            const unsigned Ph = P >> s;
            int gtb = 0, eqb = 0;
            #pragma unroll
            for (int j = 0; j < 7; j++) {
                const int d = j * 32 + lane;
                const bool gt = (d < DIM) && ((key[j] >> s) > Ph);
                const bool eq = ((actm >> j) & 1u) != 0u;
                const unsigned mg = __ballot_sync(FULLM, gt);
                const unsigned me = __ballot_sync(FULLM, eq);
                const int gtp = gtb + __popc(mg & lt);
                const int eqp = eqb + __popc(me & lt);
                if (gt || (eq && eqp < k)) {
                    const int rank = gtp + min(eqp, k);
                    atomicAdd(&hist[(rank * DIM + d) >> 1], inc);
                }
                gtb += __popc(mg);
                eqb += __popc(me);
            }
        }

        r = rn;
        #pragma unroll
        for (int j = 0; j < 7; j++) nv[j] = pv[j];
    }

    // Flush: packed-u32 REDG into the global accumulator (no return value).
    __syncthreads();
    for (int i = tid; i < HISTW; i += 256) {
        const unsigned h = hist[i];
        if (h) atomicAdd(&g_acc[b][i], h);
    }
}

__global__ __launch_bounds__(256)
void finalize_kernel(float* __restrict__ out) {
    const int b   = blockIdx.y;
    const int off = blockIdx.x * 256 + threadIdx.x;
    if (off >= HISTW) return;
    const unsigned s = g_acc[b][off];
    g_acc[b][off] = 0u;                       // reset for next graph replay
    const float invn = 1.0f / (float)NSAMP;
    float2 o;
    o.x = (float)(s & 0xFFFFu) * invn;
    o.y = (float)(s >> 16) * invn;
    ((float2*)out)[(size_t)b * HISTW + off] = o;
}

extern "C" void kernel_launch(void* const* d_in, const int* in_sizes, int n_in,
                              void* d_out, int out_size) {
    const float* x     = (const float*)d_in[0];
    const float* noise = (const float*)d_in[1];
    if (n_in >= 2 && in_sizes[0] > in_sizes[1]) {
        x     = (const float*)d_in[1];
        noise = (const float*)d_in[0];
    }
    float* out = (float*)d_out;

    dim3 mg(COPIES, BATCH, 1);                 // 640 blocks x 256 threads
    ptopk_main<<<mg, 256>>>(x, noise);
    dim3 gg((HISTW + 255) / 256, BATCH, 1);    // 19 x 64 finalize blocks
    finalize_kernel<<<gg, 256>>>(out);
}

// round 12
// speedup vs baseline: 1.1558x; 1.1558x over previous
#include <cuda_runtime.h>

// PerturbedTopK: x (64,196) f32, noise (64,500,196) f32.
// out[b,k,d] = mean_n [ sorted(top49_idx(x_b + 0.05*noise_bn))[k] == d ].
//
// R12: grid (10,64) x 256 threads; each block handles 50 rows of one batch in
// a u16-packed shared histogram (halves <= 50: no carry), then flushes the
// nonzero cells DIRECTLY into out with float atomicAdd(count/500) — <= 10
// adds per output cell, each addend an exact integer times 1/500. Output is
// zeroed by cudaMemsetAsync; no scratch, no merge/finalize kernels.
// Per-row: integer-key boundary-jump select seeded from the batch threshold
// of x (seed count fused into key build in the float domain); +-1 bookkeeping
// with a single verification recount (skipped when the seed count is already
// exact); ties/cap -> exact MSB radix fallback with index-order tie-break.

#define BATCH 64
#define NSAMP 500
#define DIM   196
#define TOPK  49
#define SIGMA 0.05f

#define COPIES 10
#define ROWS_PB (NSAMP / COPIES)   // 50
#define HISTN (TOPK * DIM)         // 9604 cells
#define HISTW (HISTN / 2)          // 4802 packed words
#define OUTN  (BATCH * TOPK * DIM)
#define FULLM 0xffffffffu
#define NEGBIG (-3.402823466e38f)

__device__ __forceinline__ unsigned f2key(float v) {
    unsigned u = __float_as_uint(v);
    return u ^ ((unsigned)((int)u >> 31) | 0x80000000u);
}
__device__ __forceinline__ float key2f(unsigned k) {
    unsigned u = (k & 0x80000000u) ? (k ^ 0x80000000u) : ~k;
    return __uint_as_float(u);
}
__device__ __forceinline__ unsigned fgt(float a, float b) {
    unsigned r;
    asm("set.gt.u32.f32 %0, %1, %2;" : "=r"(r) : "f"(a), "f"(b));
    return r;
}
__device__ __forceinline__ unsigned ugt(unsigned a, unsigned b) {
    unsigned r;
    asm("set.gt.u32.u32 %0, %1, %2;" : "=r"(r) : "r"(a), "r"(b));
    return r;
}

__global__ __launch_bounds__(256)
void ptopk_main(const float* __restrict__ x,
                const float* __restrict__ noise,
                float* __restrict__ out) {
    __shared__ __align__(16) unsigned hist[HISTW];
    __shared__ unsigned sKseed;
    __shared__ float sTseed;

    const int tid  = threadIdx.x;
    const int wid  = tid >> 5;
    const int lane = tid & 31;
    const int copy = blockIdx.x;
    const int b    = blockIdx.y;
    const unsigned lt  = (1u << lane) - 1u;
    const unsigned inc = 1u << ((lane & 1) << 4);   // u16 half by d parity

    for (int i = tid; i < HISTW; i += 256) hist[i] = 0;

    // x row resident in registers.
    float xv[7];
    #pragma unroll
    for (int j = 0; j < 7; j++) {
        const int d = j * 32 + lane;
        xv[j] = (d < DIM) ? x[b * DIM + d] : NEGBIG;
    }

    // Warp 0: batch seed threshold from x (hint only — any value is safe).
    if (wid == 0) {
        float piv = 0.674f;
        #pragma unroll 1
        for (int it = 0; it < 16; ++it) {
            unsigned a = 0;
            #pragma unroll
            for (int j = 0; j < 7; j++) a += fgt(xv[j], piv);
            const int c = -(int)__reduce_add_sync(FULLM, (int)a);
            if (c == TOPK) break;
            const int dd = c - TOPK;
            if (dd > 3 || dd < -3) {
                piv = fmaf((float)dd, 0.0161f, piv);       // Newton step
            } else if (dd > 0) {
                unsigned mk = 0xFFFFFFFFu;
                #pragma unroll
                for (int j = 0; j < 7; j++)
                    mk = min(mk, (xv[j] > piv) ? f2key(xv[j]) : 0xFFFFFFFFu);
                piv = key2f(__reduce_min_sync(FULLM, mk));
            } else {
                unsigned Mk = 0u;
                #pragma unroll
                for (int j = 0; j < 7; j++)
                    Mk = max(Mk, (xv[j] > piv) ? 0u : f2key(xv[j]));
                piv = key2f(__reduce_max_sync(FULLM, Mk) - 1u);
            }
        }
        if (lane == 0) { sTseed = piv; sKseed = f2key(piv); }
    }
    __syncthreads();
    const unsigned Kseed = sKseed;
    const float   Tseed  = sTseed;

    const size_t rowbase = (size_t)b * NSAMP + (size_t)copy * ROWS_PB;

    int r = wid;
    float nv[7];
    {
        const float* nr = noise + (rowbase + r) * DIM;
        #pragma unroll
        for (int j = 0; j < 7; j++) {
            const int d = j * 32 + lane;
            nv[j] = (d < DIM) ? nr[d] : 0.0f;
        }
    }

    #pragma unroll 1
    while (r < ROWS_PB) {
        const int rn = r + 8;
        float pv[7];
        if (rn < ROWS_PB) {                        // prefetch next row
            const float* nr2 = noise + (rowbase + rn) * DIM;
            #pragma unroll
            for (int j = 0; j < 7; j++) {
                const int d = j * 32 + lane;
                pv[j] = (d < DIM) ? nr2[d] : 0.0f;
            }
        }

        // Keys + fused seed count (float domain; key>Kseed <=> val>Tseed).
        unsigned key[7];
        unsigned a = 0;
        #pragma unroll
        for (int j = 0; j < 7; j++) {
            const int d = j * 32 + lane;
            const float v = fmaf(nv[j], SIGMA, xv[j]);
            key[j] = (d < DIM) ? f2key(v) : 0u;
            a += (d < DIM) ? fgt(v, Tseed) : 0u;   // -1 per hit
        }
        int c = -(int)__reduce_add_sync(FULLM, (int)a);

        // ---- boundary jumps: +-1 bookkeeping; verify only if we jumped ----
        unsigned Kthr = Kseed;
        int cv = c;                                // valid if no jumps taken
        if (c != TOPK) {
            #pragma unroll 1
            for (int it = 0; it < 12 && c != TOPK; ++it) {
                if (c > TOPK) {
                    unsigned mk = 0xFFFFFFFFu;     // min selected key
                    #pragma unroll
                    for (int j = 0; j < 7; j++)
                        mk = min(mk, (key[j] > Kthr) ? key[j] : 0xFFFFFFFFu);
                    Kthr = __reduce_min_sync(FULLM, mk);
                    c -= 1;                        // exact if keys distinct
                } else {
                    unsigned Mk = 0u;              // max unselected key
                    #pragma unroll
                    for (int j = 0; j < 7; j++)
                        Mk = max(Mk, (key[j] > Kthr) ? 0u : key[j]);
                    Kthr = __reduce_max_sync(FULLM, Mk) - 1u;
                    c += 1;                        // exact if keys distinct
                }
            }
            unsigned a2 = 0;                       // single verification
            #pragma unroll
            for (int j = 0; j < 7; j++) a2 += ugt(key[j], Kthr);
            cv = -(int)__reduce_add_sync(FULLM, (int)a2);
        }

        if (cv == TOPK) {
            // Exactly TOPK strictly above: rank by ascending index.
            int base = 0;
            #pragma unroll
            for (int j = 0; j < 7; j++) {
                const int d = j * 32 + lane;
                const bool s = key[j] > Kthr;
                const unsigned mb = __ballot_sync(FULLM, s);
                if (s) {
                    const int rank = base + __popc(mb & lt);
                    atomicAdd(&hist[(rank * DIM + d) >> 1], inc);
                }
                base += __popc(mb);
            }
        } else {
            // ---- exact MSB radix fallback with index-order tie-break ----
            unsigned actm = (6 * 32 + lane < DIM) ? 0x7Fu : 0x3Fu;
            int k = TOPK, matching = DIM, s = 0;
            unsigned P = 0u;
            #pragma unroll 1
            for (int bit = 31; bit >= 0; --bit) {
                const unsigned m = 1u << bit;
                int cc = 0;
                #pragma unroll
                for (int j = 0; j < 7; j++)
                    cc += (((actm >> j) & 1u) && (key[j] & m)) ? 1 : 0;
                cc = __reduce_add_sync(FULLM, cc);
                if (cc >= k) {
                    P |= m; matching = cc;
                    #pragma unroll
                    for (int j = 0; j < 7; j++)
                        if (!(key[j] & m)) actm &= ~(1u << j);
                } else {
                    k -= cc; matching -= cc;
                    #pragma unroll
                    for (int j = 0; j < 7; j++)
                        if (key[j] & m) actm &= ~(1u << j);
                }
                s = bit;
                if (matching == k) break;
            }
            const unsigned Ph = P >> s;
            int gtb = 0, eqb = 0;
            #pragma unroll
            for (int j = 0; j < 7; j++) {
                const int d = j * 32 + lane;
                const bool gt = (d < DIM) && ((key[j] >> s) > Ph);
                const bool eq = ((actm >> j) & 1u) != 0u;
                const unsigned mg = __ballot_sync(FULLM, gt);
                const unsigned me = __ballot_sync(FULLM, eq);
                const int gtp = gtb + __popc(mg & lt);
                const int eqp = eqb + __popc(me & lt);
                if (gt || (eq && eqp < k)) {
                    const int rank = gtp + min(eqp, k);
                    atomicAdd(&hist[(rank * DIM + d) >> 1], inc);
                }
                gtb += __popc(mg);
                eqb += __popc(me);
            }
        }

        r = rn;
        #pragma unroll
        for (int j = 0; j < 7; j++) nv[j] = pv[j];
    }

    // Flush nonzero cells straight into out (<=10 float adds per cell; each
    // addend is an exact small-integer multiple of 1/500).
    __syncthreads();
    const float invn = 1.0f / (float)NSAMP;
    float* __restrict__ outb = out + (size_t)b * HISTN;
    for (int i = tid; i < HISTW; i += 256) {
        const unsigned h = hist[i];
        if (h) {
            const unsigned lo = h & 0xFFFFu, hi = h >> 16;
            if (lo) atomicAdd(outb + 2 * i,     (float)lo * invn);
            if (hi) atomicAdd(outb + 2 * i + 1, (float)hi * invn);
        }
    }
}

extern "C" void kernel_launch(void* const* d_in, const int* in_sizes, int n_in,
                              void* d_out, int out_size) {
    const float* x     = (const float*)d_in[0];
    const float* noise = (const float*)d_in[1];
    if (n_in >= 2 && in_sizes[0] > in_sizes[1]) {
        x     = (const float*)d_in[1];
        noise = (const float*)d_in[0];
    }
    float* out = (float*)d_out;

    cudaMemsetAsync(out, 0, (size_t)OUTN * sizeof(float));
    dim3 mg(COPIES, BATCH, 1);                 // 640 blocks x 256 threads
    ptopk_main<<<mg, 256>>>(x, noise, out);
}

// round 13
// speedup vs baseline: 1.2083x; 1.0455x over previous
#include <cuda_runtime.h>

// PerturbedTopK: x (64,196) f32, noise (64,500,196) f32.
// out[b,k,d] = mean_n [ sorted(top49_idx(x_b + 0.05*noise_bn))[k] == d ].
//
// R13: grid (10,64) x 256; each block: 50 rows of one batch -> u16-packed
// shared histogram (halves <= 50: no carry) -> direct float atomicAdd flush
// into out (<=10 adds/cell, each an exact integer multiple of 1/500).
// Float-domain threshold search (no persistent key array -> low regs):
// count at batch seed T_b (from x alone); boundary jumps via on-the-fly
// f2key reductions (min selected / pred of max unselected), +-1 bookkeeping,
// single verification count with the SAME float compare used by the emit —
// a verified count==49 is a valid top-49 upper set. Ties/cap -> exact MSB
// radix fallback (keys rebuilt inline) with index-order tie-break.

#define BATCH 64
#define NSAMP 500
#define DIM   196
#define TOPK  49
#define SIGMA 0.05f

#define COPIES 10
#define ROWS_PB (NSAMP / COPIES)   // 50
#define HISTN (TOPK * DIM)         // 9604
#define HISTW (HISTN / 2)          // 4802 packed words
#define OUTN  (BATCH * TOPK * DIM)
#define FULLM 0xffffffffu
#define NEGBIG (-3.402823466e38f)

__device__ __forceinline__ unsigned f2key(float v) {
    unsigned u = __float_as_uint(v);
    return u ^ ((unsigned)((int)u >> 31) | 0x80000000u);
}
__device__ __forceinline__ float key2f(unsigned k) {
    unsigned u = (k & 0x80000000u) ? (k ^ 0x80000000u) : ~k;
    return __uint_as_float(u);
}
__device__ __forceinline__ unsigned fgt(float a, float b) {
    unsigned r;
    asm("set.gt.u32.f32 %0, %1, %2;" : "=r"(r) : "f"(a), "f"(b));
    return r;
}

__global__ __launch_bounds__(256)
void ptopk_main(const float* __restrict__ x,
                const float* __restrict__ noise,
                float* __restrict__ out) {
    __shared__ __align__(16) unsigned hist[HISTW];
    __shared__ float sTseed;

    const int tid  = threadIdx.x;
    const int wid  = tid >> 5;
    const int lane = tid & 31;
    const int copy = blockIdx.x;
    const int b    = blockIdx.y;
    const unsigned lt  = (1u << lane) - 1u;
    const unsigned inc = 1u << ((lane & 1) << 4);   // u16 half by d parity

    for (int i = tid; i < HISTW; i += 256) hist[i] = 0;

    // x row resident in registers (padding -> NEGBIG so pads never select).
    float xv[7];
    #pragma unroll
    for (int j = 0; j < 7; j++) {
        const int d = j * 32 + lane;
        xv[j] = (d < DIM) ? x[b * DIM + d] : NEGBIG;
    }

    // Warp 0: batch seed threshold from x (hint only — any value is safe).
    if (wid == 0) {
        float piv = 0.674f;
        #pragma unroll 1
        for (int it = 0; it < 16; ++it) {
            unsigned a = 0;
            #pragma unroll
            for (int j = 0; j < 7; j++) a += fgt(xv[j], piv);
            const int c = -(int)__reduce_add_sync(FULLM, (int)a);
            if (c == TOPK) break;
            const int dd = c - TOPK;
            if (dd > 3 || dd < -3) {
                piv = fmaf((float)dd, 0.0161f, piv);
            } else if (dd > 0) {
                unsigned mk = 0xFFFFFFFFu;
                #pragma unroll
                for (int j = 0; j < 7; j++)
                    mk = min(mk, (xv[j] > piv) ? f2key(xv[j]) : 0xFFFFFFFFu);
                piv = key2f(__reduce_min_sync(FULLM, mk));
            } else {
                unsigned Mk = 0u;
                #pragma unroll
                for (int j = 0; j < 7; j++)
                    Mk = max(Mk, (xv[j] > piv) ? 0u : f2key(xv[j]));
                piv = key2f(__reduce_max_sync(FULLM, Mk) - 1u);
            }
        }
        if (lane == 0) sTseed = piv;
    }
    __syncthreads();
    const float Tseed = sTseed;

    const size_t rowbase = (size_t)b * NSAMP + (size_t)copy * ROWS_PB;

    int r = wid;
    float cur[7];
    {
        const float* nr = noise + (rowbase + r) * DIM;
        #pragma unroll
        for (int j = 0; j < 7; j++) {
            const int d = j * 32 + lane;
            cur[j] = (d < DIM) ? nr[d] : 0.0f;
        }
    }

    #pragma unroll 1
    while (r < ROWS_PB) {
        const int rn = r + 8;
        float pv[7];
        if (rn < ROWS_PB) {                        // prefetch next row
            const float* nr2 = noise + (rowbase + rn) * DIM;
            #pragma unroll
            for (int j = 0; j < 7; j++) {
                const int d = j * 32 + lane;
                pv[j] = (d < DIM) ? nr2[d] : 0.0f;
            }
        }

        // val = x + SIGMA*noise, in place (padding stays NEGBIG via xv).
        #pragma unroll
        for (int j = 0; j < 7; j++) cur[j] = fmaf(cur[j], SIGMA, xv[j]);

        // Count at the seed threshold.
        unsigned a = 0;
        #pragma unroll
        for (int j = 0; j < 7; j++) a += fgt(cur[j], Tseed);   // -1 per hit
        int c = -(int)__reduce_add_sync(FULLM, (int)a);

        // ---- boundary jumps (keys on the fly); verify only if jumped ----
        float Tthr = Tseed;
        int cv = c;
        if (c != TOPK) {
            #pragma unroll 1
            for (int it = 0; it < 12 && c != TOPK; ++it) {
                if (c > TOPK) {
                    unsigned mk = 0xFFFFFFFFu;     // min key among selected
                    #pragma unroll
                    for (int j = 0; j < 7; j++)
                        mk = min(mk, (cur[j] > Tthr) ? f2key(cur[j]) : 0xFFFFFFFFu);
                    Tthr = key2f(__reduce_min_sync(FULLM, mk));
                    c -= 1;                        // exact if values distinct
                } else {
                    unsigned Mk = 0u;              // max key among unselected
                    #pragma unroll
                    for (int j = 0; j < 7; j++)
                        Mk = max(Mk, (cur[j] > Tthr) ? 0u : f2key(cur[j]));
                    Tthr = key2f(__reduce_max_sync(FULLM, Mk) - 1u);
                    c += 1;                        // exact if values distinct
                }
            }
            unsigned a2 = 0;                       // single verification
            #pragma unroll
            for (int j = 0; j < 7; j++) a2 += fgt(cur[j], Tthr);
            cv = -(int)__reduce_add_sync(FULLM, (int)a2);
        }

        if (cv == TOPK) {
            // Exactly TOPK strictly above Tthr (same compare as the count):
            // a valid top-49 upper set. Rank by ascending index.
            int base = 0;
            #pragma unroll
            for (int j = 0; j < 7; j++) {
                const int d = j * 32 + lane;
                const bool s = cur[j] > Tthr;
                const unsigned mb = __ballot_sync(FULLM, s);
                if (s) {
                    const int rank = base + __popc(mb & lt);
                    atomicAdd(&hist[(rank * DIM + d) >> 1], inc);
                }
                base += __popc(mb);
            }
        } else {
            // ---- exact MSB radix fallback (keys inline), index tie-break ----
            unsigned key[7];
            #pragma unroll
            for (int j = 0; j < 7; j++)
                key[j] = (j * 32 + lane < DIM) ? f2key(cur[j]) : 0u;
            unsigned actm = (6 * 32 + lane < DIM) ? 0x7Fu : 0x3Fu;
            int k = TOPK, matching = DIM, s = 0;
            unsigned P = 0u;
            #pragma unroll 1
            for (int bit = 31; bit >= 0; --bit) {
                const unsigned m = 1u << bit;
                int cc = 0;
                #pragma unroll
                for (int j = 0; j < 7; j++)
                    cc += (((actm >> j) & 1u) && (key[j] & m)) ? 1 : 0;
                cc = __reduce_add_sync(FULLM, cc);
                if (cc >= k) {
                    P |= m; matching = cc;
                    #pragma unroll
                    for (int j = 0; j < 7; j++)
                        if (!(key[j] & m)) actm &= ~(1u << j);
                } else {
                    k -= cc; matching -= cc;
                    #pragma unroll
                    for (int j = 0; j < 7; j++)
                        if (key[j] & m) actm &= ~(1u << j);
                }
                s = bit;
                if (matching == k) break;
            }
            const unsigned Ph = P >> s;
            int gtb = 0, eqb = 0;
            #pragma unroll
            for (int j = 0; j < 7; j++) {
                const int d = j * 32 + lane;
                const bool gt = (d < DIM) && ((key[j] >> s) > Ph);
                const bool eq = ((actm >> j) & 1u) != 0u;
                const unsigned mg = __ballot_sync(FULLM, gt);
                const unsigned me = __ballot_sync(FULLM, eq);
                const int gtp = gtb + __popc(mg & lt);
                const int eqp = eqb + __popc(me & lt);
                if (gt || (eq && eqp < k)) {
                    const int rank = gtp + min(eqp, k);
                    atomicAdd(&hist[(rank * DIM + d) >> 1], inc);
                }
                gtb += __popc(mg);
                eqb += __popc(me);
            }
        }

        r = rn;
        #pragma unroll
        for (int j = 0; j < 7; j++) cur[j] = pv[j];
    }

    // Flush nonzero cells straight into out (exact multiples of 1/500).
    __syncthreads();
    const float invn = 1.0f / (float)NSAMP;
    float* __restrict__ outb = out + (size_t)b * HISTN;
    for (int i = tid; i < HISTW; i += 256) {
        const unsigned h = hist[i];
        if (h) {
            const unsigned lo = h & 0xFFFFu, hi = h >> 16;
            if (lo) atomicAdd(outb + 2 * i,     (float)lo * invn);
            if (hi) atomicAdd(outb + 2 * i + 1, (float)hi * invn);
        }
    }
}

extern "C" void kernel_launch(void* const* d_in, const int* in_sizes, int n_in,
                              void* d_out, int out_size) {
    const float* x     = (const float*)d_in[0];
    const float* noise = (const float*)d_in[1];
    if (n_in >= 2 && in_sizes[0] > in_sizes[1]) {
        x     = (const float*)d_in[1];
        noise = (const float*)d_in[0];
    }
    float* out = (float*)d_out;

    cudaMemsetAsync(out, 0, (size_t)OUTN * sizeof(float));
    dim3 mg(COPIES, BATCH, 1);                 // 640 blocks x 256 threads
    ptopk_main<<<mg, 256>>>(x, noise, out);
}

// round 14
// speedup vs baseline: 1.2429x; 1.0286x over previous
#include <cuda_runtime.h>

// PerturbedTopK: x (64,196) f32, noise (64,500,196) f32.
// out[b,k,d] = mean_n [ sorted(top49_idx(x_b + 0.05*noise_bn))[k] == d ].
//
// R14: grid (20,64) x 256; each block: 25 rows of one batch -> u16-packed
// shared histogram (halves <= 25: no carry) -> direct float atomicAdd flush
// into memset-zeroed out (<=20 adds/cell, exact multiples of 1/500).
// Hot loop (R11-proven shape, key domain): load noise -> keys (noise regs
// die) -> count at batch-seeded threshold -> +-1-bookkeeping boundary jumps
// -> single verification (skipped when seed count already exact) -> ballot-
// rank emit. Rows failing verification (ties) or the cap only set a bit in
// a shared mask; AFTER the loop warp 0 reloads those rows and runs the
// exact MSB radix select (index-order tie-break) — keeps fallback register
// pressure out of the hot loop.

#define BATCH 64
#define NSAMP 500
#define DIM   196
#define TOPK  49
#define SIGMA 0.05f

#define COPIES 20
#define ROWS_PB (NSAMP / COPIES)   // 25
#define HISTN (TOPK * DIM)         // 9604
#define HISTW (HISTN / 2)          // 4802 packed words
#define OUTN  (BATCH * TOPK * DIM)
#define FULLM 0xffffffffu
#define NEGBIG (-3.402823466e38f)

__device__ __forceinline__ unsigned f2key(float v) {
    unsigned u = __float_as_uint(v);
    return u ^ ((unsigned)((int)u >> 31) | 0x80000000u);
}
__device__ __forceinline__ float key2f(unsigned k) {
    unsigned u = (k & 0x80000000u) ? (k ^ 0x80000000u) : ~k;
    return __uint_as_float(u);
}
__device__ __forceinline__ unsigned fgt(float a, float b) {
    unsigned r;
    asm("set.gt.u32.f32 %0, %1, %2;" : "=r"(r) : "f"(a), "f"(b));
    return r;
}
__device__ __forceinline__ unsigned ugt(unsigned a, unsigned b) {
    unsigned r;
    asm("set.gt.u32.u32 %0, %1, %2;" : "=r"(r) : "r"(a), "r"(b));
    return r;
}

__global__ __launch_bounds__(256)
void ptopk_main(const float* __restrict__ x,
                const float* __restrict__ noise,
                float* __restrict__ out) {
    __shared__ __align__(16) unsigned hist[HISTW];
    __shared__ unsigned sKseed;
    __shared__ unsigned fmask;          // bit r set => row r needs fallback

    const int tid  = threadIdx.x;
    const int wid  = tid >> 5;
    const int lane = tid & 31;
    const int copy = blockIdx.x;
    const int b    = blockIdx.y;
    const unsigned lt  = (1u << lane) - 1u;
    const unsigned inc = 1u << ((lane & 1) << 4);   // u16 half by d parity

    for (int i = tid; i < HISTW; i += 256) hist[i] = 0;
    if (tid == 0) fmask = 0u;

    // x row resident in registers (padding -> NEGBIG so pads never select).
    float xv[7];
    #pragma unroll
    for (int j = 0; j < 7; j++) {
        const int d = j * 32 + lane;
        xv[j] = (d < DIM) ? x[b * DIM + d] : NEGBIG;
    }

    // Warp 0: batch seed threshold from x (hint only — any value is safe).
    if (wid == 0) {
        float piv = 0.674f;
        #pragma unroll 1
        for (int it = 0; it < 16; ++it) {
            unsigned a = 0;
            #pragma unroll
            for (int j = 0; j < 7; j++) a += fgt(xv[j], piv);
            const int c = -(int)__reduce_add_sync(FULLM, (int)a);
            if (c == TOPK) break;
            const int dd = c - TOPK;
            if (dd > 3 || dd < -3) {
                piv = fmaf((float)dd, 0.0161f, piv);
            } else if (dd > 0) {
                unsigned mk = 0xFFFFFFFFu;
                #pragma unroll
                for (int j = 0; j < 7; j++)
                    mk = min(mk, (xv[j] > piv) ? f2key(xv[j]) : 0xFFFFFFFFu);
                piv = key2f(__reduce_min_sync(FULLM, mk));
            } else {
                unsigned Mk = 0u;
                #pragma unroll
                for (int j = 0; j < 7; j++)
                    Mk = max(Mk, (xv[j] > piv) ? 0u : f2key(xv[j]));
                piv = key2f(__reduce_max_sync(FULLM, Mk) - 1u);
            }
        }
        if (lane == 0) sKseed = f2key(piv);
    }
    __syncthreads();
    const unsigned Kseed = sKseed;

    const size_t rowbase = (size_t)b * NSAMP + (size_t)copy * ROWS_PB;

    int r = wid;
    float nv[7];
    if (r < ROWS_PB) {
        const float* nr = noise + (rowbase + r) * DIM;
        #pragma unroll
        for (int j = 0; j < 7; j++) {
            const int d = j * 32 + lane;
            nv[j] = (d < DIM) ? nr[d] : 0.0f;
        }
    }

    #pragma unroll 1
    while (r < ROWS_PB) {
        const int rn = r + 8;
        float pv[7];
        if (rn < ROWS_PB) {                        // prefetch next row
            const float* nr2 = noise + (rowbase + rn) * DIM;
            #pragma unroll
            for (int j = 0; j < 7; j++) {
                const int d = j * 32 + lane;
                pv[j] = (d < DIM) ? nr2[d] : 0.0f;
            }
        }

        // Keys (noise registers die here). Padding -> key 0.
        unsigned key[7];
        #pragma unroll
        for (int j = 0; j < 7; j++) {
            const int d = j * 32 + lane;
            key[j] = (d < DIM) ? f2key(fmaf(nv[j], SIGMA, xv[j])) : 0u;
        }

        // Count at the seed threshold.
        unsigned a = 0;
        #pragma unroll
        for (int j = 0; j < 7; j++) a += ugt(key[j], Kseed);   // -1 per hit
        int c = -(int)__reduce_add_sync(FULLM, (int)a);

        // ---- boundary jumps: +-1 bookkeeping; verify only if jumped ----
        unsigned Kthr = Kseed;
        int cv = c;
        if (c != TOPK) {
            #pragma unroll 1
            for (int it = 0; it < 12 && c != TOPK; ++it) {
                if (c > TOPK) {
                    unsigned mk = 0xFFFFFFFFu;     // min selected key
                    #pragma unroll
                    for (int j = 0; j < 7; j++)
                        mk = min(mk, (key[j] > Kthr) ? key[j] : 0xFFFFFFFFu);
                    Kthr = __reduce_min_sync(FULLM, mk);
                    c -= 1;                        // exact if keys distinct
                } else {
                    unsigned Mk = 0u;              // max unselected key
                    #pragma unroll
                    for (int j = 0; j < 7; j++)
                        Mk = max(Mk, (key[j] > Kthr) ? 0u : key[j]);
                    Kthr = __reduce_max_sync(FULLM, Mk) - 1u;
                    c += 1;                        // exact if keys distinct
                }
            }
            unsigned a2 = 0;                       // single verification
            #pragma unroll
            for (int j = 0; j < 7; j++) a2 += ugt(key[j], Kthr);
            cv = -(int)__reduce_add_sync(FULLM, (int)a2);
        }

        if (cv == TOPK) {
            // Exactly TOPK strictly above: rank by ascending index.
            int base = 0;
            #pragma unroll
            for (int j = 0; j < 7; j++) {
                const int d = j * 32 + lane;
                const bool s = key[j] > Kthr;
                const unsigned mb = __ballot_sync(FULLM, s);
                if (s) {
                    const int rank = base + __popc(mb & lt);
                    atomicAdd(&hist[(rank * DIM + d) >> 1], inc);
                }
                base += __popc(mb);
            }
        } else if (lane == 0) {
            atomicOr(&fmask, 1u << r);             // defer to post-loop
        }

        r = rn;
        #pragma unroll
        for (int j = 0; j < 7; j++) nv[j] = pv[j];
    }

    __syncthreads();

    // ---- deferred exact radix fallback (warp 0; expected empty) ----
    if (wid == 0 && fmask != 0u) {
        unsigned fm = fmask;
        #pragma unroll 1
        while (fm != 0u) {
            const int rr = __ffs(fm) - 1;
            fm &= fm - 1u;
            const float* nr = noise + (rowbase + rr) * DIM;
            unsigned key[7];
            #pragma unroll
            for (int j = 0; j < 7; j++) {
                const int d = j * 32 + lane;
                key[j] = (d < DIM) ? f2key(fmaf(nr[d], SIGMA, xv[j])) : 0u;
            }
            unsigned actm = (6 * 32 + lane < DIM) ? 0x7Fu : 0x3Fu;
            int k = TOPK, matching = DIM, s = 0;
            unsigned P = 0u;
            #pragma unroll 1
            for (int bit = 31; bit >= 0; --bit) {
                const unsigned m = 1u << bit;
                int cc = 0;
                #pragma unroll
                for (int j = 0; j < 7; j++)
                    cc += (((actm >> j) & 1u) && (key[j] & m)) ? 1 : 0;
                cc = __reduce_add_sync(FULLM, cc);
                if (cc >= k) {
                    P |= m; matching = cc;
                    #pragma unroll
                    for (int j = 0; j < 7; j++)
                        if (!(key[j] & m)) actm &= ~(1u << j);
                } else {
                    k -= cc; matching -= cc;
                    #pragma unroll
                    for (int j = 0; j < 7; j++)
                        if (key[j] & m) actm &= ~(1u << j);
                }
                s = bit;
                if (matching == k) break;
            }
            const unsigned Ph = P >> s;
            int gtb = 0, eqb = 0;
            #pragma unroll
            for (int j = 0; j < 7; j++) {
                const int d = j * 32 + lane;
                const bool gt = (d < DIM) && ((key[j] >> s) > Ph);
                const bool eq = ((actm >> j) & 1u) != 0u;
                const unsigned mg = __ballot_sync(FULLM, gt);
                const unsigned me = __ballot_sync(FULLM, eq);
                const int gtp = gtb + __popc(mg & lt);
                const int eqp = eqb + __popc(me & lt);
                if (gt || (eq && eqp < k)) {
                    const int rank = gtp + min(eqp, k);
                    atomicAdd(&hist[(rank * DIM + d) >> 1], inc);
                }
                gtb += __popc(mg);
                eqb += __popc(me);
            }
        }
    }
    __syncthreads();

    // Flush nonzero cells straight into out (exact multiples of 1/500).
    const float invn = 1.0f / (float)NSAMP;
    float* __restrict__ outb = out + (size_t)b * HISTN;
    for (int i = tid; i < HISTW; i += 256) {
        const unsigned h = hist[i];
        if (h) {
            const unsigned lo = h & 0xFFFFu, hi = h >> 16;
            if (lo) atomicAdd(outb + 2 * i,     (float)lo * invn);
            if (hi) atomicAdd(outb + 2 * i + 1, (float)hi * invn);
        }
    }
}

extern "C" void kernel_launch(void* const* d_in, const int* in_sizes, int n_in,
                              void* d_out, int out_size) {
    const float* x     = (const float*)d_in[0];
    const float* noise = (const float*)d_in[1];
    if (n_in >= 2 && in_sizes[0] > in_sizes[1]) {
        x     = (const float*)d_in[1];
        noise = (const float*)d_in[0];
    }
    float* out = (float*)d_out;

    cudaMemsetAsync(out, 0, (size_t)OUTN * sizeof(float));
    dim3 mg(COPIES, BATCH, 1);                 // 1280 blocks x 256 threads
    ptopk_main<<<mg, 256>>>(x, noise, out);
}

// round 16
// speedup vs baseline: 1.3574x; 1.0922x over previous
#include <cuda_runtime.h>

// PerturbedTopK: x (64,196) f32, noise (64,500,196) f32.
// out[b,k,d] = mean_n [ sorted(top49_idx(x_b + 0.05*noise_bn))[k] == d ].
//
// R15 (re-bench after infra failure): prep kernel (64 blocks): zero out[b] +
// warp0 computes batch seed threshold T_b from x. Main: 1 row/warp
// (grid 125x64 x128), FLOAT4 loads (2 LDG.128/lane instead of 7 LDG.32 ->
// MLP_p1 7->2), key-domain boundary-jump select (+-1 bookkeeping, single
// verify, skip if seed count exact), and a PARALLEL 8-ballot emit: exact
// ascending-index ranks via two-sided popc masks (no serial ballot chain).
// Fallback (ties/cap): exact MSB radix on the same layout, gt/eq ranks via
// the same two-sided formula -> index-order tie-break preserved.
//
// Layout: lane L, slot s = c*4+m  ->  d = c*128 + 4L + m   (c in {0,1});
// chunk 1 valid only for L <= 16 (d <= 195). All chunk-0 d < all chunk-1 d.

#define BATCH 64
#define NSAMP 500
#define DIM   196
#define TOPK  49
#define SIGMA 0.05f

#define OUTN  (BATCH * TOPK * DIM)
#define FULLM 0xffffffffu
#define NEGBIG (-3.402823466e38f)

__device__ float g_Tb[BATCH];

__device__ __forceinline__ unsigned f2key(float v) {
    unsigned u = __float_as_uint(v);
    return u ^ ((unsigned)((int)u >> 31) | 0x80000000u);
}
__device__ __forceinline__ float key2f(unsigned k) {
    unsigned u = (k & 0x80000000u) ? (k ^ 0x80000000u) : ~k;
    return __uint_as_float(u);
}
__device__ __forceinline__ unsigned fgt(float a, float b) {
    unsigned r;
    asm("set.gt.u32.f32 %0, %1, %2;" : "=r"(r) : "f"(a), "f"(b));
    return r;
}
__device__ __forceinline__ unsigned ugt(unsigned a, unsigned b) {
    unsigned r;
    asm("set.gt.u32.u32 %0, %1, %2;" : "=r"(r) : "r"(a), "r"(b));
    return r;
}

// ---- prep: zero out[b] (warps 1-7) + seed T_b from x (warp 0) ----
__global__ __launch_bounds__(256)
void prep_kernel(const float* __restrict__ x, float* __restrict__ out) {
    const int b = blockIdx.x;
    const int tid = threadIdx.x;

    if (tid >= 32) {
        float4* ob = reinterpret_cast<float4*>(out + (size_t)b * (TOPK * DIM));
        const float4 z = make_float4(0.f, 0.f, 0.f, 0.f);
        for (int i = tid - 32; i < (TOPK * DIM) / 4; i += 224) ob[i] = z;
        return;
    }
    const int lane = tid;
    float val[7];
    #pragma unroll
    for (int j = 0; j < 7; j++) {
        const int d = j * 32 + lane;
        val[j] = (d < DIM) ? x[b * DIM + d] : NEGBIG;
    }
    float piv = 0.674f;
    #pragma unroll 1
    for (int it = 0; it < 40; ++it) {
        unsigned a = 0;
        #pragma unroll
        for (int j = 0; j < 7; j++) a += fgt(val[j], piv);
        const int c = -(int)__reduce_add_sync(FULLM, (int)a);
        if (c == TOPK) break;
        if (c > TOPK) {
            unsigned mk = 0xFFFFFFFFu;
            #pragma unroll
            for (int j = 0; j < 7; j++)
                mk = min(mk, (val[j] > piv) ? f2key(val[j]) : 0xFFFFFFFFu);
            piv = key2f(__reduce_min_sync(FULLM, mk));
        } else {
            unsigned Mk = 0u;
            #pragma unroll
            for (int j = 0; j < 7; j++)
                Mk = max(Mk, (val[j] > piv) ? 0u : f2key(val[j]));
            piv = key2f(__reduce_max_sync(FULLM, Mk) - 1u);
        }
    }
    if (lane == 0) g_Tb[b] = piv;   // hint only; any value is safe
}

__global__ __launch_bounds__(128)
void ptopk_kernel(const float* __restrict__ x,
                  const float* __restrict__ noise,
                  float* __restrict__ out) {
    const int wid  = threadIdx.x >> 5;
    const int lane = threadIdx.x & 31;
    const int b    = blockIdx.y;
    const int rib  = blockIdx.x * 4 + wid;      // row in batch, [0,500)

    const unsigned lt  = (1u << lane) - 1u;
    const unsigned lte = lt | (1u << lane);
    const bool hasC1 = (lane <= 16);            // chunk-1 validity
    const float invn = 1.0f / (float)NSAMP;
    float* __restrict__ outb = out + (size_t)b * (TOPK * DIM);

    // float4 loads: x (L2-hot) and noise row.
    const float4* x4 = reinterpret_cast<const float4*>(x + b * DIM);
    const float4* n4 = reinterpret_cast<const float4*>(
        noise + ((size_t)b * NSAMP + rib) * DIM);

    const float4 nx0 = n4[lane];
    const float4 xa0 = x4[lane];
    float4 nx1, xa1;
    if (hasC1) { nx1 = n4[32 + lane]; xa1 = x4[32 + lane]; }
    else       { nx1 = make_float4(0,0,0,0); xa1 = make_float4(NEGBIG,NEGBIG,NEGBIG,NEGBIG); }

    // Keys: slot s=c*4+m -> d=c*128+4*lane+m. Padding -> key 0.
    unsigned key[8];
    key[0] = f2key(fmaf(nx0.x, SIGMA, xa0.x));
    key[1] = f2key(fmaf(nx0.y, SIGMA, xa0.y));
    key[2] = f2key(fmaf(nx0.z, SIGMA, xa0.z));
    key[3] = f2key(fmaf(nx0.w, SIGMA, xa0.w));
    key[4] = hasC1 ? f2key(fmaf(nx1.x, SIGMA, xa1.x)) : 0u;
    key[5] = hasC1 ? f2key(fmaf(nx1.y, SIGMA, xa1.y)) : 0u;
    key[6] = hasC1 ? f2key(fmaf(nx1.z, SIGMA, xa1.z)) : 0u;
    key[7] = hasC1 ? f2key(fmaf(nx1.w, SIGMA, xa1.w)) : 0u;

    // Count at the batch-seeded threshold.
    const unsigned Kseed = f2key(g_Tb[b]);
    unsigned Kthr = Kseed;
    unsigned a = 0;
    #pragma unroll
    for (int s = 0; s < 8; s++) a += ugt(key[s], Kthr);      // -1 per hit
    int c = -(int)__reduce_add_sync(FULLM, (int)a);

    // Boundary jumps: +-1 bookkeeping; verify only if we jumped.
    int cv = c;
    if (c != TOPK) {
        #pragma unroll 1
        for (int it = 0; it < 12 && c != TOPK; ++it) {
            if (c > TOPK) {
                unsigned mk = 0xFFFFFFFFu;                   // min selected
                #pragma unroll
                for (int s = 0; s < 8; s++)
                    mk = min(mk, (key[s] > Kthr) ? key[s] : 0xFFFFFFFFu);
                Kthr = __reduce_min_sync(FULLM, mk);
                c -= 1;
            } else {
                unsigned Mk = 0u;                            // max unselected
                #pragma unroll
                for (int s = 0; s < 8; s++)
                    Mk = max(Mk, (key[s] > Kthr) ? 0u : key[s]);
                Kthr = __reduce_max_sync(FULLM, Mk) - 1u;
                c += 1;
            }
        }
        unsigned a2 = 0;
        #pragma unroll
        for (int s = 0; s < 8; s++) a2 += ugt(key[s], Kthr);
        cv = -(int)__reduce_add_sync(FULLM, (int)a2);
    }

    if (cv == TOPK) {
        // ---- parallel-ballot emit: exact ascending-d ranks ----
        unsigned bb[8];
        #pragma unroll
        for (int s = 0; s < 8; s++)
            bb[s] = __ballot_sync(FULLM, key[s] > Kthr);
        const int t0 = __popc(bb[0]) + __popc(bb[1]) + __popc(bb[2]) + __popc(bb[3]);
        #pragma unroll
        for (int cch = 0; cch < 2; cch++) {
            #pragma unroll
            for (int m = 0; m < 4; m++) {
                const int s = cch * 4 + m;
                if (key[s] > Kthr) {
                    int rank = cch ? t0 : 0;
                    #pragma unroll
                    for (int mp = 0; mp < 4; mp++)
                        rank += __popc(bb[cch * 4 + mp] & (mp < m ? lte : lt));
                    const int d = cch * 128 + 4 * lane + m;
                    atomicAdd(outb + rank * DIM + d, invn);
                }
            }
        }
        return;
    }

    // ---- exact MSB radix fallback, index-order tie-break (cold) ----
    unsigned actm = hasC1 ? 0xFFu : 0x0Fu;
    int k = TOPK, matching = DIM, sh = 0;
    unsigned P = 0u;
    #pragma unroll 1
    for (int bit = 31; bit >= 0; --bit) {
        const unsigned m = 1u << bit;
        int cc = 0;
        #pragma unroll
        for (int s = 0; s < 8; s++)
            cc += (((actm >> s) & 1u) && (key[s] & m)) ? 1 : 0;
        cc = __reduce_add_sync(FULLM, cc);
        if (cc >= k) {
            P |= m; matching = cc;
            #pragma unroll
            for (int s = 0; s < 8; s++)
                if (!(key[s] & m)) actm &= ~(1u << s);
        } else {
            k -= cc; matching -= cc;
            #pragma unroll
            for (int s = 0; s < 8; s++)
                if (key[s] & m) actm &= ~(1u << s);
        }
        sh = bit;
        if (matching == k) break;
    }
    const unsigned Ph = P >> sh;
    unsigned gb[8], eb[8];
    #pragma unroll
    for (int s = 0; s < 8; s++) {
        const bool valid = (s < 4) || hasC1;
        gb[s] = __ballot_sync(FULLM, valid && ((key[s] >> sh) > Ph));
        eb[s] = __ballot_sync(FULLM, ((actm >> s) & 1u) != 0u);
    }
    const int g0 = __popc(gb[0]) + __popc(gb[1]) + __popc(gb[2]) + __popc(gb[3]);
    const int e0 = __popc(eb[0]) + __popc(eb[1]) + __popc(eb[2]) + __popc(eb[3]);
    #pragma unroll
    for (int cch = 0; cch < 2; cch++) {
        #pragma unroll
        for (int m = 0; m < 4; m++) {
            const int s = cch * 4 + m;
            const bool valid = (s < 4) || hasC1;
            const bool gt = valid && ((key[s] >> sh) > Ph);
            const bool eq = ((actm >> s) & 1u) != 0u;
            if (gt || eq) {
                int gtp = cch ? g0 : 0, eqp = cch ? e0 : 0;
                #pragma unroll
                for (int mp = 0; mp < 4; mp++) {
                    gtp += __popc(gb[cch * 4 + mp] & (mp < m ? lte : lt));
                    eqp += __popc(eb[cch * 4 + mp] & (mp < m ? lte : lt));
                }
                if (gt || (eq && eqp < k)) {
                    const int rank = gtp + min(eqp, k);
                    const int d = cch * 128 + 4 * lane + m;
                    atomicAdd(outb + rank * DIM + d, invn);
                }
            }
        }
    }
}

extern "C" void kernel_launch(void* const* d_in, const int* in_sizes, int n_in,
                              void* d_out, int out_size) {
    const float* x     = (const float*)d_in[0];
    const float* noise = (const float*)d_in[1];
    if (n_in >= 2 && in_sizes[0] > in_sizes[1]) {
        x     = (const float*)d_in[1];
        noise = (const float*)d_in[0];
    }
    float* out = (float*)d_out;

    prep_kernel<<<BATCH, 256>>>(x, out);
    dim3 grid(125, BATCH, 1);   // 125*4 = 500 rows per batch
    ptopk_kernel<<<grid, 128>>>(x, noise, out);
}